// round 12
// baseline (speedup 1.0000x reference)
#include <cuda_runtime.h>
#include <math.h>

// Problem constants
#define BB 32
#define TT 4096
#define NN 11
#define FF 16
#define HH 32
#define TPB 32                 // t-values per block
#define THREADS 176            // (TPB/2) * NN ; each thread does 2 t-rows
#define ROW 176                // NN*FF floats per (b,t)

typedef unsigned long long u64;

// ---- packed f32x2 helpers (sm_100+) ----
__device__ __forceinline__ u64 fma2(u64 a, u64 b, u64 c) {
    u64 d;
    asm("fma.rn.f32x2 %0, %1, %2, %3;" : "=l"(d) : "l"(a), "l"(b), "l"(c));
    return d;
}
__device__ __forceinline__ u64 add2(u64 a, u64 b) {
    u64 d;
    asm("add.rn.f32x2 %0, %1, %2;" : "=l"(d) : "l"(a), "l"(b));
    return d;
}
__device__ __forceinline__ u64 mul2(u64 a, u64 b) {
    u64 d;
    asm("mul.rn.f32x2 %0, %1, %2;" : "=l"(d) : "l"(a), "l"(b));
    return d;
}
__device__ __forceinline__ u64 dup2(float v) {
    u64 r;
    asm("mov.b64 %0, {%1, %1};" : "=l"(r) : "f"(v));
    return r;
}
__device__ __forceinline__ u64 pk2(float lo, float hi) {
    u64 r;
    asm("mov.b64 %0, {%1, %2};" : "=l"(r) : "f"(lo), "f"(hi));
    return r;
}
__device__ __forceinline__ float2 upk2(u64 v) {
    float2 f;
    asm("mov.b64 {%0, %1}, %2;" : "=f"(f.x), "=f"(f.y) : "l"(v));
    return f;
}
__device__ __forceinline__ float rcpf(float x) {
    float r;
    asm("rcp.approx.f32 %0, %1;" : "=f"(r) : "f"(x));
    return r;
}
__device__ __forceinline__ float ex2f(float x) {
    float r;
    asm("ex2.approx.f32 %0, %1;" : "=f"(r) : "f"(x));
    return r;
}
__device__ __forceinline__ float csignf(float mag, float sgn) {
    // (mag & 0x7fffffff) | (sgn & 0x80000000)  -> single LOP3
    unsigned m = __float_as_uint(mag), s = __float_as_uint(sgn);
    return __uint_as_float((m & 0x7fffffffu) | (s & 0x80000000u));
}

// ---- packed GELU on pre-scaled input U = v/sqrt(2) (pair) ----
// gelu(v) = 0.70710678 * u * (1 + erf(u)),  erf via A&S 7.1.26 (|err|<=1.5e-7)
__device__ __forceinline__ u64 gelu2p(u64 U) {
    const u64 ABS2 = 0x7FFFFFFF7FFFFFFFULL;
    const u64 ONE2 = 0x3F8000003F800000ULL;
    // |u| (2x LOP32)
    u64 au = U & ABS2;
    // d = 1 + 0.3275911*|u| ; t = 1/d (scalar MUFU x2)
    u64 d = fma2(dup2(0.3275911f), au, ONE2);
    float2 df = upk2(d);
    u64 t = pk2(rcpf(df.x), rcpf(df.y));
    // Horner with negated A&S coeffs: p = -q(t)
    u64 p = fma2(dup2(-1.061405429f), t, dup2(1.453152027f));
    p = fma2(p, t, dup2(-1.421413741f));
    p = fma2(p, t, dup2(0.284496736f));
    p = fma2(p, t, dup2(-0.254829592f));
    p = mul2(p, t);
    // e = exp(-u^2) = 2^(-log2e * u^2)
    u64 u2 = mul2(U, U);
    u64 w  = mul2(dup2(-1.4426950408889634f), u2);
    float2 wf = upk2(w);
    u64 e = pk2(ex2f(wf.x), ex2f(wf.y));
    // r = 1 - q*e = fma(p, e, 1)   in [0,1]
    u64 r = fma2(p, e, ONE2);
    // erf = copysign(r, u) per element (LOP3 each)
    float2 rf = upk2(r);
    float2 uf = upk2(U);
    u64 erf = pk2(csignf(rf.x, uf.x), csignf(rf.y, uf.y));
    // gelu = h + h*erf,  h = 0.70710678*u
    u64 h = mul2(dup2(0.70710678118654752f), U);
    return fma2(h, erf, h);
}

__global__ __launch_bounds__(THREADS, 4)
void fused_proj_mlp_kernel(
    const float* __restrict__ x,          // [B,T,N,F]
    const int*   __restrict__ lab_idx,    // [B]
    const float* __restrict__ projection, // [LABS,N,N]
    const float* __restrict__ bias,       // [LABS,1,N,F]
    const float* __restrict__ w1,         // [F,H]
    const float* __restrict__ b1,         // [H]
    const float* __restrict__ ln_g,       // [H]
    const float* __restrict__ ln_b,       // [H]
    const float* __restrict__ w2,         // [H,F]
    const float* __restrict__ b2,         // [F]
    float* __restrict__ out)              // [B,T,N,F]
{
    __shared__ __align__(16) float xs[TPB * ROW];     // flat x tile
    __shared__ __align__(16) float Ws[NN * NN];
    __shared__ __align__(16) float bias_s[NN * FF];
    __shared__ __align__(16) float w1s[FF * HH];
    __shared__ __align__(16) float w2s[HH * FF];
    __shared__ __align__(16) float b1s[HH];
    __shared__ __align__(16) float gs[HH];
    __shared__ __align__(16) float bls[HH];            // pre-scaled by 1/sqrt(2)
    __shared__ __align__(16) float b2s[FF];

    const int tid = threadIdx.x;
    const int b   = blockIdx.y;
    const int t0  = blockIdx.x * TPB;
    const int lab = lab_idx[b];

    // ---- stage x tile (1408 float4, 8 per thread) ----
    {
        const float4* xg = (const float4*)(x + ((size_t)(b * TT + t0)) * ROW);
        float4* xd = (float4*)xs;
        #pragma unroll
        for (int i = 0; i < 8; i++) {
            int idx = tid + i * THREADS;
            xd[idx] = xg[idx];
        }
    }
    // ---- stage params ----
    if (tid < NN * NN)   Ws[tid]     = projection[lab * NN * NN + tid];
    if (tid < NN * FF)   bias_s[tid] = bias[lab * NN * FF + tid];
    #pragma unroll
    for (int i = tid; i < FF * HH; i += THREADS) { w1s[i] = w1[i]; w2s[i] = w2[i]; }
    if (tid < HH) {
        b1s[tid] = b1[tid];
        gs[tid]  = ln_g[tid];
        bls[tid] = ln_b[tid] * 0.70710678118654752f;   // fold 1/sqrt(2) into LN bias
    }
    if (tid < FF) b2s[tid] = b2[tid];
    __syncthreads();

    const int m  = tid % NN;       // output channel (same for both rows)
    const int tl = tid / NN;       // 0..15 ; rows tl and tl+16

    // ---- projection: acc[f] = bias[m,f] + sum_n x[t,n,f] * W[n,m] ----
    u64 wnp[NN];
    #pragma unroll
    for (int n = 0; n < NN; n++) wnp[n] = dup2(Ws[n * NN + m]);

    u64 aA[8], aB[8];
    {
        const ulonglong2* bv = (const ulonglong2*)(bias_s + m * FF);
        #pragma unroll
        for (int q = 0; q < 4; q++) {
            ulonglong2 v = bv[q];
            aA[2*q] = v.x; aA[2*q+1] = v.y;
            aB[2*q] = v.x; aB[2*q+1] = v.y;
        }
    }
    {
        const ulonglong2* xA = (const ulonglong2*)(xs + tl * ROW);
        const ulonglong2* xB = (const ulonglong2*)(xs + (tl + 16) * ROW);
        #pragma unroll
        for (int n = 0; n < NN; n++) {
            u64 w = wnp[n];
            #pragma unroll
            for (int q = 0; q < 4; q++) {
                ulonglong2 va = xA[n * 4 + q];
                ulonglong2 vb = xB[n * 4 + q];
                aA[2*q]   = fma2(va.x, w, aA[2*q]);
                aA[2*q+1] = fma2(va.y, w, aA[2*q+1]);
                aB[2*q]   = fma2(vb.x, w, aB[2*q]);
                aB[2*q+1] = fma2(vb.y, w, aB[2*q+1]);
            }
        }
    }

    // ---- MLP1: h[j] = b1[j] + sum_f ov[f] * w1[f,j] (weights shared by both rows) ----
    u64 hA[16], hB[16];
    {
        const ulonglong2* bv = (const ulonglong2*)b1s;
        #pragma unroll
        for (int q = 0; q < 8; q++) {
            ulonglong2 v = bv[q];
            hA[2*q] = v.x; hA[2*q+1] = v.y;
            hB[2*q] = v.x; hB[2*q+1] = v.y;
        }
    }
    #pragma unroll
    for (int p = 0; p < 8; p++) {                 // f = 2p, 2p+1
        float2 ua = upk2(aA[p]);
        float2 ub = upk2(aB[p]);
        #pragma unroll
        for (int s = 0; s < 2; s++) {
            int f = 2 * p + s;
            u64 ba = dup2(s == 0 ? ua.x : ua.y);
            u64 bb = dup2(s == 0 ? ub.x : ub.y);
            const ulonglong2* wr = (const ulonglong2*)(w1s + f * HH);
            #pragma unroll
            for (int q = 0; q < 8; q++) {
                ulonglong2 wv = wr[q];
                hA[2*q]   = fma2(ba, wv.x, hA[2*q]);
                hA[2*q+1] = fma2(ba, wv.y, hA[2*q+1]);
                hB[2*q]   = fma2(bb, wv.x, hB[2*q]);
                hB[2*q+1] = fma2(bb, wv.y, hB[2*q+1]);
            }
        }
    }

    // ---- LayerNorm (fully packed) ----
    float muA, rA, muB, rB;
    {
        u64 SA = hA[0], SB = hB[0];
        u64 QA = mul2(hA[0], hA[0]), QB = mul2(hB[0], hB[0]);
        #pragma unroll
        for (int k = 1; k < 16; k++) {
            SA = add2(SA, hA[k]);       SB = add2(SB, hB[k]);
            QA = fma2(hA[k], hA[k], QA); QB = fma2(hB[k], hB[k], QB);
        }
        float2 sa = upk2(SA), sb = upk2(SB), qa = upk2(QA), qb = upk2(QB);
        float sAf = sa.x + sa.y, sBf = sb.x + sb.y;
        float qAf = qa.x + qa.y, qBf = qb.x + qb.y;
        muA = sAf * (1.f / HH);  muB = sBf * (1.f / HH);
        // rstd pre-scaled by 1/sqrt(2): LN+scale produces u = v/sqrt(2) directly
        rA = rsqrtf(qAf * (1.f / HH) - muA * muA + 1e-5f) * 0.70710678118654752f;
        rB = rsqrtf(qBf * (1.f / HH) - muB * muB + 1e-5f) * 0.70710678118654752f;
    }
    // normalize + affine (pre-scaled) + packed GELU; h := gelu(ln(h))
    {
        const u64 rA2 = dup2(rA), rB2 = dup2(rB);
        const u64 nmA = dup2(-muA), nmB = dup2(-muB);
        const ulonglong2* gv = (const ulonglong2*)gs;
        const ulonglong2* bv = (const ulonglong2*)bls;
        #pragma unroll
        for (int q = 0; q < 8; q++) {
            ulonglong2 gg = gv[q];
            ulonglong2 bb = bv[q];
            // c1 = rstd'*g ; c0 = -mu*c1 + b' ; u = h*c1 + c0  (u = v/sqrt(2))
            u64 c1A0 = mul2(rA2, gg.x), c1A1 = mul2(rA2, gg.y);
            u64 c1B0 = mul2(rB2, gg.x), c1B1 = mul2(rB2, gg.y);
            u64 c0A0 = fma2(nmA, c1A0, bb.x), c0A1 = fma2(nmA, c1A1, bb.y);
            u64 c0B0 = fma2(nmB, c1B0, bb.x), c0B1 = fma2(nmB, c1B1, bb.y);
            hA[2*q]   = gelu2p(fma2(hA[2*q],   c1A0, c0A0));
            hA[2*q+1] = gelu2p(fma2(hA[2*q+1], c1A1, c0A1));
            hB[2*q]   = gelu2p(fma2(hB[2*q],   c1B0, c0B0));
            hB[2*q+1] = gelu2p(fma2(hB[2*q+1], c1B1, c0B1));
        }
    }

    // ---- MLP2: y[f] = b2[f] + sum_j g[j] * w2[j,f] ----
    u64 yA[8], yB[8];
    {
        const ulonglong2* bv = (const ulonglong2*)b2s;
        #pragma unroll
        for (int q = 0; q < 4; q++) {
            ulonglong2 v = bv[q];
            yA[2*q] = v.x; yA[2*q+1] = v.y;
            yB[2*q] = v.x; yB[2*q+1] = v.y;
        }
    }
    #pragma unroll
    for (int p = 0; p < 16; p++) {               // j = 2p, 2p+1
        float2 ga = upk2(hA[p]);
        float2 gb = upk2(hB[p]);
        #pragma unroll
        for (int s = 0; s < 2; s++) {
            int j = 2 * p + s;
            u64 ba = dup2(s == 0 ? ga.x : ga.y);
            u64 bb = dup2(s == 0 ? gb.x : gb.y);
            const ulonglong2* wr = (const ulonglong2*)(w2s + j * FF);
            #pragma unroll
            for (int q = 0; q < 4; q++) {
                ulonglong2 wv = wr[q];
                yA[2*q]   = fma2(ba, wv.x, yA[2*q]);
                yA[2*q+1] = fma2(ba, wv.y, yA[2*q+1]);
                yB[2*q]   = fma2(bb, wv.x, yB[2*q]);
                yB[2*q+1] = fma2(bb, wv.y, yB[2*q+1]);
            }
        }
    }

    // ---- store both rows, float4 ----
    float* ygA = out + (((size_t)(b * TT + t0 + tl)) * NN + m) * FF;
    float* ygB = out + (((size_t)(b * TT + t0 + tl + 16)) * NN + m) * FF;
    #pragma unroll
    for (int k = 0; k < 4; k++) {
        float2 a0 = upk2(yA[2*k]); float2 a1 = upk2(yA[2*k+1]);
        float2 b0 = upk2(yB[2*k]); float2 b1v = upk2(yB[2*k+1]);
        *(float4*)(ygA + 4*k) = make_float4(a0.x, a0.y, a1.x, a1.y);
        *(float4*)(ygB + 4*k) = make_float4(b0.x, b0.y, b1v.x, b1v.y);
    }
}

extern "C" void kernel_launch(void* const* d_in, const int* in_sizes, int n_in,
                              void* d_out, int out_size) {
    const float* x          = (const float*)d_in[0];
    const int*   lab_idx    = (const int*)  d_in[1];
    const float* projection = (const float*)d_in[2];
    const float* bias       = (const float*)d_in[3];
    const float* w1         = (const float*)d_in[4];
    const float* b1         = (const float*)d_in[5];
    const float* ln_g       = (const float*)d_in[6];
    const float* ln_b       = (const float*)d_in[7];
    const float* w2         = (const float*)d_in[8];
    const float* b2         = (const float*)d_in[9];
    float* out = (float*)d_out;

    dim3 grid(TT / TPB, BB);   // (128, 32)
    fused_proj_mlp_kernel<<<grid, THREADS>>>(
        x, lab_idx, projection, bias, w1, b1, ln_g, ln_b, w2, b2, out);
}

// round 13
// speedup vs baseline: 1.4146x; 1.4146x over previous
#include <cuda_runtime.h>
#include <math.h>

// Problem constants
#define BB 32
#define TT 4096
#define NN 11
#define FF 16
#define HH 32
#define TPB 32                 // t-values per block
#define THREADS 176            // (TPB/2) * NN ; each thread does 2 t-rows
#define ROW 176                // NN*FF floats per (b,t)

typedef unsigned long long u64;

// ---- packed f32x2 helpers (sm_100+) ----
__device__ __forceinline__ u64 fma2(u64 a, u64 b, u64 c) {
    u64 d;
    asm("fma.rn.f32x2 %0, %1, %2, %3;" : "=l"(d) : "l"(a), "l"(b), "l"(c));
    return d;
}
__device__ __forceinline__ u64 add2(u64 a, u64 b) {
    u64 d;
    asm("add.rn.f32x2 %0, %1, %2;" : "=l"(d) : "l"(a), "l"(b));
    return d;
}
__device__ __forceinline__ u64 mul2(u64 a, u64 b) {
    u64 d;
    asm("mul.rn.f32x2 %0, %1, %2;" : "=l"(d) : "l"(a), "l"(b));
    return d;
}
__device__ __forceinline__ u64 dup2(float v) {
    u64 r;
    asm("mov.b64 %0, {%1, %1};" : "=l"(r) : "f"(v));
    return r;
}
__device__ __forceinline__ u64 pk2(float lo, float hi) {
    u64 r;
    asm("mov.b64 %0, {%1, %2};" : "=l"(r) : "f"(lo), "f"(hi));
    return r;
}
__device__ __forceinline__ float2 upk2(u64 v) {
    float2 f;
    asm("mov.b64 {%0, %1}, %2;" : "=f"(f.x), "=f"(f.y) : "l"(v));
    return f;
}
__device__ __forceinline__ float rcpf(float x) {
    float r;
    asm("rcp.approx.f32 %0, %1;" : "=f"(r) : "f"(x));
    return r;
}
__device__ __forceinline__ float ex2f(float x) {
    float r;
    asm("ex2.approx.f32 %0, %1;" : "=f"(r) : "f"(x));
    return r;
}
__device__ __forceinline__ float csignf(float mag, float sgn) {
    // (mag & 0x7fffffff) | (sgn & 0x80000000)  -> single LOP3
    unsigned m = __float_as_uint(mag), s = __float_as_uint(sgn);
    return __uint_as_float((m & 0x7fffffffu) | (s & 0x80000000u));
}

// ---- packed GELU on pre-scaled input U = v/sqrt(2) (pair) ----
// gelu(v) = 0.70710678 * u * (1 + erf(u)),  erf via A&S 7.1.26 (|err|<=1.5e-7)
__device__ __forceinline__ u64 gelu2p(u64 U) {
    const u64 ABS2 = 0x7FFFFFFF7FFFFFFFULL;
    const u64 ONE2 = 0x3F8000003F800000ULL;
    // |u| (1x LOP.64 / 2x LOP32)
    u64 au = U & ABS2;
    // d = 1 + 0.3275911*|u| ; t = 1/d (scalar MUFU x2)
    u64 d = fma2(dup2(0.3275911f), au, ONE2);
    float2 df = upk2(d);
    u64 t = pk2(rcpf(df.x), rcpf(df.y));
    // Horner with negated A&S coeffs: p = -q(t)
    u64 p = fma2(dup2(-1.061405429f), t, dup2(1.453152027f));
    p = fma2(p, t, dup2(-1.421413741f));
    p = fma2(p, t, dup2(0.284496736f));
    p = fma2(p, t, dup2(-0.254829592f));
    p = mul2(p, t);
    // e = exp(-u^2) = 2^(-log2e * u^2)
    u64 u2 = mul2(U, U);
    u64 w  = mul2(dup2(-1.4426950408889634f), u2);
    float2 wf = upk2(w);
    u64 e = pk2(ex2f(wf.x), ex2f(wf.y));
    // r = 1 - q*e = fma(p, e, 1)   in [0,1]
    u64 r = fma2(p, e, ONE2);
    // erf = copysign(r, u) per element (LOP3 each)
    float2 rf = upk2(r);
    float2 uf = upk2(U);
    u64 erf = pk2(csignf(rf.x, uf.x), csignf(rf.y, uf.y));
    // gelu = h + h*erf,  h = 0.70710678*u
    u64 h = mul2(dup2(0.70710678118654752f), U);
    return fma2(h, erf, h);
}

__global__ __launch_bounds__(THREADS, 3)
void fused_proj_mlp_kernel(
    const float* __restrict__ x,          // [B,T,N,F]
    const int*   __restrict__ lab_idx,    // [B]
    const float* __restrict__ projection, // [LABS,N,N]
    const float* __restrict__ bias,       // [LABS,1,N,F]
    const float* __restrict__ w1,         // [F,H]
    const float* __restrict__ b1,         // [H]
    const float* __restrict__ ln_g,       // [H]
    const float* __restrict__ ln_b,       // [H]
    const float* __restrict__ w2,         // [H,F]
    const float* __restrict__ b2,         // [F]
    float* __restrict__ out)              // [B,T,N,F]
{
    __shared__ __align__(16) float xs[TPB * ROW];     // flat x tile
    __shared__ __align__(16) float Ws[NN * NN];
    __shared__ __align__(16) float bias_s[NN * FF];
    __shared__ __align__(16) float w1s[FF * HH];
    __shared__ __align__(16) float w2s[HH * FF];
    __shared__ __align__(16) float b1s[HH];
    __shared__ __align__(16) float gs[HH];
    __shared__ __align__(16) float bls[HH];            // pre-scaled by 1/sqrt(2)
    __shared__ __align__(16) float b2s[FF];

    const int tid = threadIdx.x;
    const int b   = blockIdx.y;
    const int t0  = blockIdx.x * TPB;
    const int lab = lab_idx[b];

    // ---- stage x tile (1408 float4, 8 per thread) ----
    {
        const float4* xg = (const float4*)(x + ((size_t)(b * TT + t0)) * ROW);
        float4* xd = (float4*)xs;
        #pragma unroll
        for (int i = 0; i < 8; i++) {
            int idx = tid + i * THREADS;
            xd[idx] = xg[idx];
        }
    }
    // ---- stage params ----
    if (tid < NN * NN)   Ws[tid]     = projection[lab * NN * NN + tid];
    if (tid < NN * FF)   bias_s[tid] = bias[lab * NN * FF + tid];
    #pragma unroll
    for (int i = tid; i < FF * HH; i += THREADS) { w1s[i] = w1[i]; w2s[i] = w2[i]; }
    if (tid < HH) {
        b1s[tid] = b1[tid];
        gs[tid]  = ln_g[tid];
        bls[tid] = ln_b[tid] * 0.70710678118654752f;   // fold 1/sqrt(2) into LN bias
    }
    if (tid < FF) b2s[tid] = b2[tid];
    __syncthreads();

    const int m  = tid % NN;       // output channel (same for both rows)
    const int tl = tid / NN;       // 0..15 ; rows tl and tl+16

    // ---- projection: acc[f] = bias[m,f] + sum_n x[t,n,f] * W[n,m] ----
    u64 wnp[NN];
    #pragma unroll
    for (int n = 0; n < NN; n++) wnp[n] = dup2(Ws[n * NN + m]);

    u64 aA[8], aB[8];
    {
        const ulonglong2* bv = (const ulonglong2*)(bias_s + m * FF);
        #pragma unroll
        for (int q = 0; q < 4; q++) {
            ulonglong2 v = bv[q];
            aA[2*q] = v.x; aA[2*q+1] = v.y;
            aB[2*q] = v.x; aB[2*q+1] = v.y;
        }
    }
    {
        const ulonglong2* xA = (const ulonglong2*)(xs + tl * ROW);
        const ulonglong2* xB = (const ulonglong2*)(xs + (tl + 16) * ROW);
        #pragma unroll
        for (int n = 0; n < NN; n++) {
            u64 w = wnp[n];
            #pragma unroll
            for (int q = 0; q < 4; q++) {
                ulonglong2 va = xA[n * 4 + q];
                ulonglong2 vb = xB[n * 4 + q];
                aA[2*q]   = fma2(va.x, w, aA[2*q]);
                aA[2*q+1] = fma2(va.y, w, aA[2*q+1]);
                aB[2*q]   = fma2(vb.x, w, aB[2*q]);
                aB[2*q+1] = fma2(vb.y, w, aB[2*q+1]);
            }
        }
    }

    // ---- MLP1: h[j] = b1[j] + sum_f ov[f] * w1[f,j] (weights shared by both rows) ----
    u64 hA[16], hB[16];
    {
        const ulonglong2* bv = (const ulonglong2*)b1s;
        #pragma unroll
        for (int q = 0; q < 8; q++) {
            ulonglong2 v = bv[q];
            hA[2*q] = v.x; hA[2*q+1] = v.y;
            hB[2*q] = v.x; hB[2*q+1] = v.y;
        }
    }
    #pragma unroll
    for (int p = 0; p < 8; p++) {                 // f = 2p, 2p+1
        float2 ua = upk2(aA[p]);
        float2 ub = upk2(aB[p]);
        #pragma unroll
        for (int s = 0; s < 2; s++) {
            int f = 2 * p + s;
            u64 ba = dup2(s == 0 ? ua.x : ua.y);
            u64 bb = dup2(s == 0 ? ub.x : ub.y);
            const ulonglong2* wr = (const ulonglong2*)(w1s + f * HH);
            #pragma unroll
            for (int q = 0; q < 8; q++) {
                ulonglong2 wv = wr[q];
                hA[2*q]   = fma2(ba, wv.x, hA[2*q]);
                hA[2*q+1] = fma2(ba, wv.y, hA[2*q+1]);
                hB[2*q]   = fma2(bb, wv.x, hB[2*q]);
                hB[2*q+1] = fma2(bb, wv.y, hB[2*q+1]);
            }
        }
    }

    // ---- LayerNorm (fully packed) ----
    float muA, rA, muB, rB;
    {
        u64 SA = hA[0], SB = hB[0];
        u64 QA = mul2(hA[0], hA[0]), QB = mul2(hB[0], hB[0]);
        #pragma unroll
        for (int k = 1; k < 16; k++) {
            SA = add2(SA, hA[k]);       SB = add2(SB, hB[k]);
            QA = fma2(hA[k], hA[k], QA); QB = fma2(hB[k], hB[k], QB);
        }
        float2 sa = upk2(SA), sb = upk2(SB), qa = upk2(QA), qb = upk2(QB);
        float sAf = sa.x + sa.y, sBf = sb.x + sb.y;
        float qAf = qa.x + qa.y, qBf = qb.x + qb.y;
        muA = sAf * (1.f / HH);  muB = sBf * (1.f / HH);
        // rstd pre-scaled by 1/sqrt(2): LN+scale produces u = v/sqrt(2) directly
        rA = rsqrtf(qAf * (1.f / HH) - muA * muA + 1e-5f) * 0.70710678118654752f;
        rB = rsqrtf(qBf * (1.f / HH) - muB * muB + 1e-5f) * 0.70710678118654752f;
    }
    // normalize + affine (pre-scaled) + packed GELU; h := gelu(ln(h))
    {
        const u64 rA2 = dup2(rA), rB2 = dup2(rB);
        const u64 nmA = dup2(-muA), nmB = dup2(-muB);
        const ulonglong2* gv = (const ulonglong2*)gs;
        const ulonglong2* bv = (const ulonglong2*)bls;
        #pragma unroll
        for (int q = 0; q < 8; q++) {
            ulonglong2 gg = gv[q];
            ulonglong2 bb = bv[q];
            // c1 = rstd'*g ; c0 = -mu*c1 + b' ; u = h*c1 + c0  (u = v/sqrt(2))
            u64 c1A0 = mul2(rA2, gg.x), c1A1 = mul2(rA2, gg.y);
            u64 c1B0 = mul2(rB2, gg.x), c1B1 = mul2(rB2, gg.y);
            u64 c0A0 = fma2(nmA, c1A0, bb.x), c0A1 = fma2(nmA, c1A1, bb.y);
            u64 c0B0 = fma2(nmB, c1B0, bb.x), c0B1 = fma2(nmB, c1B1, bb.y);
            hA[2*q]   = gelu2p(fma2(hA[2*q],   c1A0, c0A0));
            hA[2*q+1] = gelu2p(fma2(hA[2*q+1], c1A1, c0A1));
            hB[2*q]   = gelu2p(fma2(hB[2*q],   c1B0, c0B0));
            hB[2*q+1] = gelu2p(fma2(hB[2*q+1], c1B1, c0B1));
        }
    }

    // ---- MLP2: y[f] = b2[f] + sum_j g[j] * w2[j,f] ----
    u64 yA[8], yB[8];
    {
        const ulonglong2* bv = (const ulonglong2*)b2s;
        #pragma unroll
        for (int q = 0; q < 4; q++) {
            ulonglong2 v = bv[q];
            yA[2*q] = v.x; yA[2*q+1] = v.y;
            yB[2*q] = v.x; yB[2*q+1] = v.y;
        }
    }
    #pragma unroll
    for (int p = 0; p < 16; p++) {               // j = 2p, 2p+1
        float2 ga = upk2(hA[p]);
        float2 gb = upk2(hB[p]);
        #pragma unroll
        for (int s = 0; s < 2; s++) {
            int j = 2 * p + s;
            u64 ba = dup2(s == 0 ? ga.x : ga.y);
            u64 bb = dup2(s == 0 ? gb.x : gb.y);
            const ulonglong2* wr = (const ulonglong2*)(w2s + j * FF);
            #pragma unroll
            for (int q = 0; q < 4; q++) {
                ulonglong2 wv = wr[q];
                yA[2*q]   = fma2(ba, wv.x, yA[2*q]);
                yA[2*q+1] = fma2(ba, wv.y, yA[2*q+1]);
                yB[2*q]   = fma2(bb, wv.x, yB[2*q]);
                yB[2*q+1] = fma2(bb, wv.y, yB[2*q+1]);
            }
        }
    }

    // ---- store both rows, float4 ----
    float* ygA = out + (((size_t)(b * TT + t0 + tl)) * NN + m) * FF;
    float* ygB = out + (((size_t)(b * TT + t0 + tl + 16)) * NN + m) * FF;
    #pragma unroll
    for (int k = 0; k < 4; k++) {
        float2 a0 = upk2(yA[2*k]); float2 a1 = upk2(yA[2*k+1]);
        float2 b0 = upk2(yB[2*k]); float2 b1v = upk2(yB[2*k+1]);
        *(float4*)(ygA + 4*k) = make_float4(a0.x, a0.y, a1.x, a1.y);
        *(float4*)(ygB + 4*k) = make_float4(b0.x, b0.y, b1v.x, b1v.y);
    }
}

extern "C" void kernel_launch(void* const* d_in, const int* in_sizes, int n_in,
                              void* d_out, int out_size) {
    const float* x          = (const float*)d_in[0];
    const int*   lab_idx    = (const int*)  d_in[1];
    const float* projection = (const float*)d_in[2];
    const float* bias       = (const float*)d_in[3];
    const float* w1         = (const float*)d_in[4];
    const float* b1         = (const float*)d_in[5];
    const float* ln_g       = (const float*)d_in[6];
    const float* ln_b       = (const float*)d_in[7];
    const float* w2         = (const float*)d_in[8];
    const float* b2         = (const float*)d_in[9];
    float* out = (float*)d_out;

    dim3 grid(TT / TPB, BB);   // (128, 32)
    fused_proj_mlp_kernel<<<grid, THREADS>>>(
        x, lab_idx, projection, bias, w1, b1, ln_g, ln_b, w2, b2, out);
}